// round 4
// baseline (speedup 1.0000x reference)
#include <cuda_runtime.h>
#include <cuda_fp16.h>

#define N_NODES 100000
#define N_EDGES 1600000
#define D 48
#define D4 (D / 4)
#define SCAN_BLOCK 1024
#define N_SBLK ((N_NODES + SCAN_BLOCK - 1) / SCAN_BLOCK)   // 98

// Device scratch (no allocations allowed):
__device__ __half g_xw[N_NODES * D];        // x @ w in fp16     (9.6 MB)
__device__ int    g_cnt[N_NODES];           // histogram -> cursor
__device__ int    g_off[N_NODES + 1];       // CSR row offsets
__device__ int    g_bsum[N_SBLK];           // scan block sums
__device__ uint2  g_rec[N_EDGES];           // (src, val) sorted by dst (12.8 MB)

// ---------------------------------------------------------------------------
__global__ void zero_cnt_kernel() {
    int i = blockIdx.x * blockDim.x + threadIdx.x;
    if (i < N_NODES) g_cnt[i] = 0;
}

// ---------------------------------------------------------------------------
// GEMM: g_xw[n] = x[n] @ w, fp32 math, fp16 store. Two nodes per thread.
// ---------------------------------------------------------------------------
__global__ void __launch_bounds__(256, 2)
gemm_kernel(const float* __restrict__ x, const float* __restrict__ w) {
    __shared__ float ws[D * D];
    for (int i = threadIdx.x; i < D * D; i += blockDim.x) ws[i] = w[i];
    __syncthreads();

    int base = blockIdx.x * (2 * blockDim.x) + threadIdx.x;
    int n0 = base;
    int n1 = base + blockDim.x;
    bool has0 = (n0 < N_NODES);
    bool has1 = (n1 < N_NODES);
    if (!has0) return;

    float4 xa[D4], xb[D4];
    const float4* xp0 = (const float4*)(x + (size_t)n0 * D);
    const float4* xp1 = (const float4*)(x + (size_t)n1 * D);
#pragma unroll
    for (int k4 = 0; k4 < D4; k4++) {
        xa[k4] = xp0[k4];
        xb[k4] = has1 ? xp1[k4] : make_float4(0.f, 0.f, 0.f, 0.f);
    }

    __half* hp0 = g_xw + (size_t)n0 * D;
    __half* hp1 = g_xw + (size_t)n1 * D;

#pragma unroll
    for (int j4 = 0; j4 < D4; j4++) {
        float a0 = 0.f, a1 = 0.f, a2 = 0.f, a3 = 0.f;
        float b0 = 0.f, b1 = 0.f, b2 = 0.f, b3 = 0.f;
#pragma unroll
        for (int k4 = 0; k4 < D4; k4++) {
            float4 va = xa[k4];
            float4 vb = xb[k4];
#pragma unroll
            for (int t = 0; t < 4; t++) {
                int k = k4 * 4 + t;
                float xav = (t == 0) ? va.x : (t == 1) ? va.y : (t == 2) ? va.z : va.w;
                float xbv = (t == 0) ? vb.x : (t == 1) ? vb.y : (t == 2) ? vb.z : vb.w;
                float4 wr = *(const float4*)(ws + k * D + j4 * 4);
                a0 = fmaf(xav, wr.x, a0);
                a1 = fmaf(xav, wr.y, a1);
                a2 = fmaf(xav, wr.z, a2);
                a3 = fmaf(xav, wr.w, a3);
                b0 = fmaf(xbv, wr.x, b0);
                b1 = fmaf(xbv, wr.y, b1);
                b2 = fmaf(xbv, wr.z, b2);
                b3 = fmaf(xbv, wr.w, b3);
            }
        }
        __half2 ha[2], hb[2];
        ha[0] = __floats2half2_rn(a0, a1);
        ha[1] = __floats2half2_rn(a2, a3);
        hb[0] = __floats2half2_rn(b0, b1);
        hb[1] = __floats2half2_rn(b2, b3);
        *(uint2*)(hp0 + j4 * 4) = *(const uint2*)ha;
        if (has1) *(uint2*)(hp1 + j4 * 4) = *(const uint2*)hb;
    }
}

// ---------------------------------------------------------------------------
// 1) histogram of dst
// ---------------------------------------------------------------------------
__global__ void hist_kernel(const int* __restrict__ dst) {
    int e = blockIdx.x * blockDim.x + threadIdx.x;
    if (e < N_EDGES) atomicAdd(&g_cnt[__ldg(dst + e)], 1);
}

// ---------------------------------------------------------------------------
// 2) exclusive scan of g_cnt -> g_off (3-kernel scan)
// ---------------------------------------------------------------------------
__global__ void scan1_kernel() {   // per-block exclusive scan, 1024 elems/block
    __shared__ int ssum[256];
    int b = blockIdx.x;
    int t = threadIdx.x;
    int base = b * SCAN_BLOCK + t * 4;

    int4 c = make_int4(0, 0, 0, 0);
    if (base + 3 < N_NODES) {
        c = *(const int4*)(g_cnt + base);
    } else {
        int* cp = (int*)&c;
        for (int i = 0; i < 4; i++)
            if (base + i < N_NODES) cp[i] = g_cnt[base + i];
    }
    int s = c.x + c.y + c.z + c.w;
    ssum[t] = s;
    __syncthreads();
    for (int off = 1; off < 256; off <<= 1) {
        int u = (t >= off) ? ssum[t - off] : 0;
        __syncthreads();
        ssum[t] += u;
        __syncthreads();
    }
    int excl = ssum[t] - s;   // exclusive prefix of this thread within block
    int p0 = excl;
    int p1 = p0 + c.x;
    int p2 = p1 + c.y;
    int p3 = p2 + c.z;
    if (base + 0 < N_NODES) g_off[base + 0] = p0;
    if (base + 1 < N_NODES) g_off[base + 1] = p1;
    if (base + 2 < N_NODES) g_off[base + 2] = p2;
    if (base + 3 < N_NODES) g_off[base + 3] = p3;
    if (t == 255) g_bsum[b] = ssum[255];
}

__global__ void scan2_kernel() {   // single-block scan of block sums
    __shared__ int s[128];
    int t = threadIdx.x;
    int v = (t < N_SBLK) ? g_bsum[t] : 0;
    s[t] = v;
    __syncthreads();
    for (int off = 1; off < 128; off <<= 1) {
        int u = (t >= off) ? s[t - off] : 0;
        __syncthreads();
        s[t] += u;
        __syncthreads();
    }
    if (t < N_SBLK) g_bsum[t] = s[t] - v;   // exclusive
}

__global__ void scan3_kernel() {   // add block bases; init cursors
    int i = blockIdx.x * blockDim.x + threadIdx.x;
    if (i < N_NODES) {
        int o = g_off[i] + g_bsum[i >> 10];
        g_off[i] = o;
        g_cnt[i] = o;                       // cursor for build
    }
    if (i == 0) g_off[N_NODES] = N_EDGES;
}

// ---------------------------------------------------------------------------
// 3) scatter edges into dst-sorted record array
// ---------------------------------------------------------------------------
__global__ void build_kernel(const int* __restrict__ src,
                             const int* __restrict__ dst,
                             const float* __restrict__ vals) {
    int e = blockIdx.x * blockDim.x + threadIdx.x;
    if (e >= N_EDGES) return;
    int d = __ldg(dst + e);
    int pos = atomicAdd(&g_cnt[d], 1);
    g_rec[pos] = make_uint2((unsigned)__ldg(src + e),
                            __float_as_uint(__ldg(vals + e)));
}

// ---------------------------------------------------------------------------
// 4) one warp per dst node: gather xw[src], accumulate in registers,
//    write relu(agg + b) once. Lanes 0..23 each own 2 columns.
// ---------------------------------------------------------------------------
__global__ void reduce_kernel(const float* __restrict__ b,
                              float* __restrict__ out) {
    int gwid = (blockIdx.x * blockDim.x + threadIdx.x) >> 5;
    int lane = threadIdx.x & 31;
    if (gwid >= N_NODES) return;

    int start = g_off[gwid];
    int end   = g_off[gwid + 1];

    float accx = 0.f, accy = 0.f;
    int i = start;
    for (; i + 1 < end; i += 2) {
        uint2 r0 = g_rec[i];
        uint2 r1 = g_rec[i + 1];
        if (lane < 24) {
            __half2 h0 = *((const __half2*)(g_xw + (size_t)r0.x * D) + lane);
            __half2 h1 = *((const __half2*)(g_xw + (size_t)r1.x * D) + lane);
            float a0 = __uint_as_float(r0.y);
            float a1 = __uint_as_float(r1.y);
            float2 f0 = __half22float2(h0);
            float2 f1 = __half22float2(h1);
            accx = fmaf(a0, f0.x, accx);
            accy = fmaf(a0, f0.y, accy);
            accx = fmaf(a1, f1.x, accx);
            accy = fmaf(a1, f1.y, accy);
        }
    }
    if (i < end) {
        uint2 r0 = g_rec[i];
        if (lane < 24) {
            __half2 h0 = *((const __half2*)(g_xw + (size_t)r0.x * D) + lane);
            float a0 = __uint_as_float(r0.y);
            float2 f0 = __half22float2(h0);
            accx = fmaf(a0, f0.x, accx);
            accy = fmaf(a0, f0.y, accy);
        }
    }

    if (lane < 24) {
        float2 bb = *(const float2*)(b + 2 * lane);
        float2 o;
        o.x = fmaxf(accx + bb.x, 0.f);
        o.y = fmaxf(accy + bb.y, 0.f);
        *(float2*)(out + (size_t)gwid * D + 2 * lane) = o;
    }
}

// ---------------------------------------------------------------------------
extern "C" void kernel_launch(void* const* d_in, const int* in_sizes, int n_in,
                              void* d_out, int out_size) {
    const float* x        = (const float*)d_in[0];
    const float* w        = (const float*)d_in[1];
    const float* b        = (const float*)d_in[2];
    const int*   edge_src = (const int*)d_in[3];
    const int*   edge_dst = (const int*)d_in[4];
    const float* adj_vals = (const float*)d_in[5];
    float* out = (float*)d_out;

    const int T = 256;

    zero_cnt_kernel<<<(N_NODES + T - 1) / T, T>>>();
    hist_kernel<<<(N_EDGES + T - 1) / T, T>>>(edge_dst);
    scan1_kernel<<<N_SBLK, 256>>>();
    scan2_kernel<<<1, 128>>>();
    scan3_kernel<<<(N_NODES + T - 1) / T, T>>>();
    {
        int nodes_per_block = 2 * T;
        gemm_kernel<<<(N_NODES + nodes_per_block - 1) / nodes_per_block, T>>>(x, w);
    }
    build_kernel<<<(N_EDGES + T - 1) / T, T>>>(edge_src, edge_dst, adj_vals);
    reduce_kernel<<<(N_NODES * 32 + T - 1) / T, T>>>(b, out);
}